// round 6
// baseline (speedup 1.0000x reference)
#include <cuda_runtime.h>
#include <cuda_bf16.h>
#include <cstdint>

// ============================================================================
// RBF kernel: out[b,c] = exp(-gamma * max(x2[b] + y2[c] - 2*x[b]·y[c], 0))
// B = C = 8192, D = 256, fp32 in/out.
//
// Base-target build (compute_103 PTX): tcgen05/TMEM unavailable -> use legacy
// tensor cores via mma.sync.m16n8k16 (bf16 in, fp32 accum) + ldmatrix from
// SW128-swizzled SMEM. fp32 row norms kept exact; only the cross term is bf16.
// ============================================================================

constexpr int NB = 8192;
constexpr int NC = 8192;
constexpr int ND = 256;
constexpr int TM = 128;
constexpr int TN = 128;

// Scratch (__device__ globals: no allocation allowed)
__device__ __nv_bfloat16 g_xb[NB * ND];
__device__ __nv_bfloat16 g_yb[NC * ND];
__device__ float g_x2[NB];
__device__ float g_y2[NC];

// ---------------------------------------------------------------------------
__device__ __forceinline__ uint32_t smem_u32(const void* p) {
    uint32_t a;
    asm("{ .reg .u64 t; cvta.to.shared.u64 t, %1; cvt.u32.u64 %0, t; }" : "=r"(a) : "l"(p));
    return a;
}

__device__ __forceinline__ uint32_t sw128(uint32_t x) { return x ^ ((x >> 3) & 0x70); }

#define STS128(addr, v) \
    asm volatile("st.shared.v4.b32 [%0], {%1, %2, %3, %4};" \
                 :: "r"(addr), "r"((v).x), "r"((v).y), "r"((v).z), "r"((v).w) : "memory")

__device__ __forceinline__ void ldsm_x4(uint32_t& r0, uint32_t& r1, uint32_t& r2,
                                        uint32_t& r3, uint32_t addr) {
    asm volatile("ldmatrix.sync.aligned.m8n8.x4.shared.b16 {%0,%1,%2,%3}, [%4];"
                 : "=r"(r0), "=r"(r1), "=r"(r2), "=r"(r3) : "r"(addr));
}

__device__ __forceinline__ void mma16816(float* c, const uint32_t* a,
                                         uint32_t b0, uint32_t b1) {
    asm volatile(
        "mma.sync.aligned.m16n8k16.row.col.f32.bf16.bf16.f32 "
        "{%0,%1,%2,%3}, {%4,%5,%6,%7}, {%8,%9}, {%0,%1,%2,%3};"
        : "+f"(c[0]), "+f"(c[1]), "+f"(c[2]), "+f"(c[3])
        : "r"(a[0]), "r"(a[1]), "r"(a[2]), "r"(a[3]), "r"(b0), "r"(b1));
}

// ---------------------------------------------------------------------------
// Kernel 1: row norms (fp32, exact) + bf16 conversion. One block per row.
// ---------------------------------------------------------------------------
__global__ void prep_kernel(const float* __restrict__ src, int which) {
    int row = blockIdx.x;
    int t = threadIdx.x;  // 0..63
    float4 v = reinterpret_cast<const float4*>(src + (size_t)row * ND)[t];

    __nv_bfloat16* dst = which ? g_yb : g_xb;
    float* nrm = which ? g_y2 : g_x2;

    __nv_bfloat162 lo = __floats2bfloat162_rn(v.x, v.y);
    __nv_bfloat162 hi = __floats2bfloat162_rn(v.z, v.w);
    uint2 pk;
    pk.x = *reinterpret_cast<unsigned int*>(&lo);
    pk.y = *reinterpret_cast<unsigned int*>(&hi);
    reinterpret_cast<uint2*>(dst + (size_t)row * ND)[t] = pk;

    float s = v.x * v.x + v.y * v.y + v.z * v.z + v.w * v.w;
    #pragma unroll
    for (int o = 16; o > 0; o >>= 1) s += __shfl_xor_sync(0xffffffffu, s, o);

    __shared__ float ws[2];
    if ((t & 31) == 0) ws[t >> 5] = s;
    __syncthreads();
    if (t == 0) nrm[row] = ws[0] + ws[1];
}

// ---------------------------------------------------------------------------
// Kernel 2: HMMA GEMM (128x128 tile, K=256 resident) + fused RBF epilogue.
// SMEM layout: x2/y2 norms, A and B as 4 SW128 slabs of [128 rows x 128B],
// then a padded fp32 staging tile for coalesced output stores.
// ---------------------------------------------------------------------------
constexpr int SLAB  = 16384;                  // 128 rows x 128 bytes
constexpr int SO_X2 = 0;                      // 128 floats
constexpr int SO_Y2 = 512;                    // 128 floats
constexpr int SO_A  = 1024;                   // 4 slabs = 65536 B
constexpr int SO_B  = SO_A + 4 * SLAB;        // 66560 (1024-aligned)
constexpr int SO_ST = SO_B + 4 * SLAB;        // 132096
constexpr int ST_PAD = 132;                   // floats per staging row (528 B, 16B-aligned)
constexpr int SMEM_TOTAL = SO_ST + 128 * ST_PAD * 4;   // 199680 bytes

__global__ void __launch_bounds__(256, 1) rbf_gemm_kernel(float* __restrict__ out,
                                                          const float* __restrict__ gptr) {
    extern __shared__ char smem[];
    uint32_t sb = smem_u32(smem);
    int tid = threadIdx.x;
    int wid = tid >> 5;      // 0..7
    int lane = tid & 31;
    int m0 = blockIdx.y * TM;
    int n0 = blockIdx.x * TN;

    // ---- Stage A (x rows) and B (y rows) tiles into swizzled slabs ----
    {
        const uint4* ga = reinterpret_cast<const uint4*>(g_xb + (size_t)m0 * ND);
        const uint4* gb = reinterpret_cast<const uint4*>(g_yb + (size_t)n0 * ND);
        #pragma unroll
        for (int i = 0; i < 16; i++) {
            int idx = tid + i * 256;          // 0..4095 16B-vectors
            int row = idx >> 5;               // 0..127
            int q   = idx & 31;               // 16B chunk within 512B row
            int slab = q >> 3;                // 0..3
            int inner = q & 7;
            uint32_t off = sw128((uint32_t)(row * 128 + inner * 16));
            uint4 va = ga[idx];
            STS128(sb + SO_A + slab * SLAB + off, va);
            uint4 vb = gb[idx];
            STS128(sb + SO_B + slab * SLAB + off, vb);
        }
    }
    if (tid < 128) {
        reinterpret_cast<float*>(smem + SO_X2)[tid] = g_x2[m0 + tid];
        reinterpret_cast<float*>(smem + SO_Y2)[tid] = g_y2[n0 + tid];
    }
    __syncthreads();

    // ---- Warp tiling: 2 warps in M x 4 warps in N; warp tile 64x32 ----
    int wm = wid & 1;        // 0..1
    int wn = wid >> 1;       // 0..3

    // Per-lane ldmatrix addresses.
    // Slab row layout: row r at byte r*128; 16B column c at sw128 -> c ^ (r&7).
    int l15 = lane & 15;
    uint32_t swz = (uint32_t)(lane & 7) * 16;     // XOR term for this lane's row
    uint32_t klane = (uint32_t)(lane & 16);       // +16B for upper-half matrices

    uint32_t rowA[4], rowB[2];
    #pragma unroll
    for (int mt = 0; mt < 4; mt++)
        rowA[mt] = (uint32_t)((wm * 64 + mt * 16 + l15) * 128);
    #pragma unroll
    for (int nt2 = 0; nt2 < 2; nt2++)
        rowB[nt2] = (uint32_t)((wn * 32 + nt2 * 16 + l15) * 128);

    float acc[4][4][4];
    #pragma unroll
    for (int mt = 0; mt < 4; mt++)
        #pragma unroll
        for (int nt = 0; nt < 4; nt++)
            #pragma unroll
            for (int e = 0; e < 4; e++) acc[mt][nt][e] = 0.0f;

    // ---- Mainloop: 16 k-steps of 16 (K = 256) ----
    #pragma unroll
    for (int kk = 0; kk < 16; kk++) {
        uint32_t slabOff = (uint32_t)(kk >> 2) * SLAB;
        uint32_t kbs = (((uint32_t)(kk & 3) * 32) + klane) ^ swz;
        uint32_t aBase = sb + SO_A + slabOff + kbs;
        uint32_t bBase = sb + SO_B + slabOff + kbs;

        uint32_t a[4][4];
        #pragma unroll
        for (int mt = 0; mt < 4; mt++)
            ldsm_x4(a[mt][0], a[mt][1], a[mt][2], a[mt][3], aBase + rowA[mt]);

        uint32_t bf[2][4];
        #pragma unroll
        for (int nt2 = 0; nt2 < 2; nt2++)
            ldsm_x4(bf[nt2][0], bf[nt2][1], bf[nt2][2], bf[nt2][3], bBase + rowB[nt2]);

        #pragma unroll
        for (int mt = 0; mt < 4; mt++) {
            #pragma unroll
            for (int nt = 0; nt < 4; nt++) {
                uint32_t b0 = bf[nt >> 1][nt & 1];        // n-tile low k-half
                uint32_t b1 = bf[nt >> 1][2 + (nt & 1)];  // high k-half
                mma16816(acc[mt][nt], a[mt], b0, b1);
            }
        }
    }

    // ---- Epilogue: sq-dist + exp into padded staging, then coalesced stores ----
    float gamma = *gptr;
    float* stage = reinterpret_cast<float*>(smem + SO_ST);
    const float* x2s = reinterpret_cast<const float*>(smem + SO_X2);
    const float* y2s = reinterpret_cast<const float*>(smem + SO_Y2);

    int grp = lane >> 2;       // 0..7
    int qd  = lane & 3;        // 0..3
    #pragma unroll
    for (int mt = 0; mt < 4; mt++) {
        int r0 = wm * 64 + mt * 16 + grp;
        int r1 = r0 + 8;
        float x2a = x2s[r0], x2b = x2s[r1];
        #pragma unroll
        for (int nt = 0; nt < 4; nt++) {
            int col = wn * 32 + nt * 8 + qd * 2;
            float yc0 = y2s[col], yc1 = y2s[col + 1];
            float* c = acc[mt][nt];
            float s00 = fmaxf(x2a + yc0 - 2.0f * c[0], 0.0f);
            float s01 = fmaxf(x2a + yc1 - 2.0f * c[1], 0.0f);
            float s10 = fmaxf(x2b + yc0 - 2.0f * c[2], 0.0f);
            float s11 = fmaxf(x2b + yc1 - 2.0f * c[3], 0.0f);
            float2 e0 = make_float2(__expf(-gamma * s00), __expf(-gamma * s01));
            float2 e1 = make_float2(__expf(-gamma * s10), __expf(-gamma * s11));
            *reinterpret_cast<float2*>(&stage[r0 * ST_PAD + col]) = e0;
            *reinterpret_cast<float2*>(&stage[r1 * ST_PAD + col]) = e1;
        }
    }
    __syncthreads();

    // Coalesced 16B stores: each warp writes contiguous 512B row segments.
    const float4* stv = reinterpret_cast<const float4*>(smem + SO_ST);
    #pragma unroll
    for (int i = 0; i < 16; i++) {
        int idx = tid + i * 256;     // 0..4095
        int row = idx >> 5;          // 0..127
        int q   = idx & 31;          // float4 index within 128-col row
        float4 v = stv[row * (ST_PAD / 4) + q];
        reinterpret_cast<float4*>(out + (size_t)(m0 + row) * NC + n0)[q + 0] = v;
        (void)0;
        // note: single store per iteration; q already spans the row
        // (kept explicit for clarity)
        // store executed above
        // -- no-op --
        ;
    }
}

// ---------------------------------------------------------------------------
extern "C" void kernel_launch(void* const* d_in, const int* in_sizes, int n_in,
                              void* d_out, int out_size) {
    const float* x = (const float*)d_in[0];
    const float* y = (const float*)d_in[1];
    const float* g = (const float*)d_in[2];
    float* out = (float*)d_out;

    cudaFuncSetAttribute(rbf_gemm_kernel,
                         cudaFuncAttributeMaxDynamicSharedMemorySize, SMEM_TOTAL);

    prep_kernel<<<NB, 64>>>(x, 0);
    prep_kernel<<<NC, 64>>>(y, 1);

    dim3 grid(NC / TN, NB / TM);
    rbf_gemm_kernel<<<grid, 256, SMEM_TOTAL>>>(out, g);
}

// round 7
// speedup vs baseline: 1.4707x; 1.4707x over previous
#include <cuda_runtime.h>
#include <cuda_bf16.h>
#include <cstdint>

// ============================================================================
// RBF kernel: out[b,c] = exp(-gamma * max(x2[b] + y2[c] - 2*x[b]·y[c], 0))
// B = C = 8192, D = 256, fp32 in/out.
//
// Base-target build (compute_103): no tcgen05. Legacy tensor cores
// (mma.sync.m16n8k16 bf16) + ldmatrix from SW128-swizzled SMEM.
// This round: cp.async double-buffered mainloop (kc=64), 2 CTAs/SM,
// permuted-B layout for direct STG.128 epilogue (no SMEM staging).
// ============================================================================

constexpr int NB = 8192;
constexpr int NC = 8192;
constexpr int ND = 256;
constexpr int TM = 128;
constexpr int TN = 128;

__device__ __nv_bfloat16 g_xb[NB * ND];
__device__ __nv_bfloat16 g_yb[NC * ND];
__device__ float g_x2[NB];
__device__ float g_y2[NC];

// ---------------------------------------------------------------------------
__device__ __forceinline__ uint32_t smem_u32(const void* p) {
    uint32_t a;
    asm("{ .reg .u64 t; cvta.to.shared.u64 t, %1; cvt.u32.u64 %0, t; }" : "=r"(a) : "l"(p));
    return a;
}

__device__ __forceinline__ uint32_t sw128(uint32_t x) { return x ^ ((x >> 3) & 0x70); }

#define CP16(dst, src) \
    asm volatile("cp.async.cg.shared.global [%0], [%1], 16;" \
                 :: "r"(dst), "l"(src) : "memory")
#define CP_COMMIT() asm volatile("cp.async.commit_group;" ::: "memory")
#define CP_WAIT1()  asm volatile("cp.async.wait_group 1;" ::: "memory")
#define CP_WAIT0()  asm volatile("cp.async.wait_group 0;" ::: "memory")

__device__ __forceinline__ void ldsm_x4(uint32_t& r0, uint32_t& r1, uint32_t& r2,
                                        uint32_t& r3, uint32_t addr) {
    asm volatile("ldmatrix.sync.aligned.m8n8.x4.shared.b16 {%0,%1,%2,%3}, [%4];"
                 : "=r"(r0), "=r"(r1), "=r"(r2), "=r"(r3) : "r"(addr));
}

__device__ __forceinline__ void mma16816(float* c, const uint32_t* a,
                                         uint32_t b0, uint32_t b1) {
    asm volatile(
        "mma.sync.aligned.m16n8k16.row.col.f32.bf16.bf16.f32 "
        "{%0,%1,%2,%3}, {%4,%5,%6,%7}, {%8,%9}, {%0,%1,%2,%3};"
        : "+f"(c[0]), "+f"(c[1]), "+f"(c[2]), "+f"(c[3])
        : "r"(a[0]), "r"(a[1]), "r"(a[2]), "r"(a[3]), "r"(b0), "r"(b1));
}

// ---------------------------------------------------------------------------
// Prep: one warp per row, fused x+y. Exact fp32 norms + bf16 conversion.
// ---------------------------------------------------------------------------
__global__ void __launch_bounds__(256) prep_kernel(const float* __restrict__ x,
                                                   const float* __restrict__ y) {
    int gw = blockIdx.x * 8 + (threadIdx.x >> 5);   // global row 0..16383
    int lane = threadIdx.x & 31;

    const float* src;
    __nv_bfloat16* dst;
    float* nrm;
    int row;
    if (gw < NB) { row = gw;      src = x; dst = g_xb; nrm = g_x2; }
    else         { row = gw - NB; src = y; dst = g_yb; nrm = g_y2; }

    const float4* s4 = reinterpret_cast<const float4*>(src + (size_t)row * ND);
    float4 v0 = s4[lane];
    float4 v1 = s4[lane + 32];

    uint2* d2 = reinterpret_cast<uint2*>(dst + (size_t)row * ND);
    __nv_bfloat162 a0 = __floats2bfloat162_rn(v0.x, v0.y);
    __nv_bfloat162 a1 = __floats2bfloat162_rn(v0.z, v0.w);
    __nv_bfloat162 b0 = __floats2bfloat162_rn(v1.x, v1.y);
    __nv_bfloat162 b1 = __floats2bfloat162_rn(v1.z, v1.w);
    uint2 pa, pb;
    pa.x = *reinterpret_cast<unsigned*>(&a0);
    pa.y = *reinterpret_cast<unsigned*>(&a1);
    pb.x = *reinterpret_cast<unsigned*>(&b0);
    pb.y = *reinterpret_cast<unsigned*>(&b1);
    d2[lane] = pa;
    d2[lane + 32] = pb;

    float s = v0.x*v0.x + v0.y*v0.y + v0.z*v0.z + v0.w*v0.w
            + v1.x*v1.x + v1.y*v1.y + v1.z*v1.z + v1.w*v1.w;
    #pragma unroll
    for (int o = 16; o > 0; o >>= 1) s += __shfl_xor_sync(0xffffffffu, s, o);
    if (lane == 0) nrm[row] = s;
}

// ---------------------------------------------------------------------------
// GEMM: 128x128 tile, kc=64 double-buffered cp.async, direct-STG epilogue.
// SMEM: [x2 512B][y2 512B][stage0: A 16KB | B 16KB][stage1: A 16KB | B 16KB]
// ---------------------------------------------------------------------------
constexpr int SO_X2   = 0;
constexpr int SO_Y2   = 512;
constexpr int SO_ST0  = 1024;
constexpr int STAGE   = 32768;      // A slab 16KB + B slab 16KB
constexpr int SMEM_TOTAL = SO_ST0 + 2 * STAGE;   // 66560 B

// B row permutation: slab row s (within a warp's 32) holds y-row pqhe(s), so
// that each thread's fragment cols from an n-tile pair are 4 consecutive
// global columns.  s bits [4]=p,[3]=h,[2:1]=q,[0]=e  ->  y bits [4]=p,[3:2]=q,[1]=h,[0]=e
__device__ __forceinline__ int b_perm(int row) {
    int s5 = row & 31;
    return (row & ~31) | (s5 & 0x10) | ((s5 & 0x6) << 1) | ((s5 & 0x8) >> 2) | (s5 & 1);
}

__global__ void __launch_bounds__(256, 2) rbf_gemm_kernel(float* __restrict__ out,
                                                          const float* __restrict__ gptr) {
    extern __shared__ char smem[];
    uint32_t sb = smem_u32(smem);
    int tid = threadIdx.x;
    int wid = tid >> 5;       // 0..7
    int lane = tid & 31;
    int m0 = blockIdx.y * TM;
    int n0 = blockIdx.x * TN;

    const char* gA = reinterpret_cast<const char*>(g_xb + (size_t)m0 * ND);
    const char* gB = reinterpret_cast<const char*>(g_yb + (size_t)n0 * ND);

    // ---- async chunk loader: chunk c (64 k) into stage st ----
    auto load_chunk = [&](int c, int st) {
        uint32_t aBase = sb + SO_ST0 + st * STAGE;
        uint32_t bBase = aBase + 16384;
        #pragma unroll
        for (int i = 0; i < 4; i++) {
            int idx = tid + i * 256;          // 0..1023
            int row = idx >> 3;               // 0..127
            int inner = idx & 7;              // 16B chunk in 128B row
            uint32_t off = sw128((uint32_t)(row * 128 + inner * 16));
            CP16(aBase + off, gA + (size_t)row * 512 + c * 128 + inner * 16);
            int yrow = b_perm(row);
            CP16(bBase + off, gB + (size_t)yrow * 512 + c * 128 + inner * 16);
        }
        CP_COMMIT();
    };

    load_chunk(0, 0);
    load_chunk(1, 1);

    if (tid < 128) {
        reinterpret_cast<float*>(smem + SO_X2)[tid] = g_x2[m0 + tid];
        reinterpret_cast<float*>(smem + SO_Y2)[tid] = g_y2[n0 + tid];
    }

    // ---- warp tiling: 2 (M) x 4 (N) warps, 64x32 each ----
    int wm = wid & 1;
    int wn = wid >> 1;
    int l15 = lane & 15;
    uint32_t swz = (uint32_t)(lane & 7) * 16;
    uint32_t klane = (uint32_t)(lane & 16);

    uint32_t rowA[4], rowB[2];
    #pragma unroll
    for (int mt = 0; mt < 4; mt++)
        rowA[mt] = (uint32_t)((wm * 64 + mt * 16 + l15) * 128);
    #pragma unroll
    for (int nt2 = 0; nt2 < 2; nt2++)
        rowB[nt2] = (uint32_t)((wn * 32 + nt2 * 16 + l15) * 128);

    float acc[4][4][4];
    #pragma unroll
    for (int mt = 0; mt < 4; mt++)
        #pragma unroll
        for (int nt = 0; nt < 4; nt++)
            #pragma unroll
            for (int e = 0; e < 4; e++) acc[mt][nt][e] = 0.0f;

    // ---- mainloop: 4 chunks x 4 k-steps ----
    #pragma unroll
    for (int c = 0; c < 4; c++) {
        if (c < 3) CP_WAIT1(); else CP_WAIT0();
        __syncthreads();

        uint32_t aSlab = sb + SO_ST0 + (c & 1) * STAGE;
        uint32_t bSlab = aSlab + 16384;

        #pragma unroll
        for (int kk = 0; kk < 4; kk++) {
            uint32_t kbs = (((uint32_t)kk * 32) + klane) ^ swz;
            uint32_t aBase = aSlab + kbs;
            uint32_t bBase = bSlab + kbs;

            uint32_t a[4][4];
            #pragma unroll
            for (int mt = 0; mt < 4; mt++)
                ldsm_x4(a[mt][0], a[mt][1], a[mt][2], a[mt][3], aBase + rowA[mt]);

            uint32_t bf[2][4];
            #pragma unroll
            for (int nt2 = 0; nt2 < 2; nt2++)
                ldsm_x4(bf[nt2][0], bf[nt2][1], bf[nt2][2], bf[nt2][3], bBase + rowB[nt2]);

            #pragma unroll
            for (int mt = 0; mt < 4; mt++) {
                #pragma unroll
                for (int nt = 0; nt < 4; nt++) {
                    uint32_t b0 = bf[nt >> 1][nt & 1];
                    uint32_t b1 = bf[nt >> 1][2 + (nt & 1)];
                    mma16816(acc[mt][nt], a[mt], b0, b1);
                }
            }
        }

        __syncthreads();
        if (c + 2 < 4) load_chunk(c + 2, c & 1);
    }

    // ---- epilogue: direct STG.128 (permuted-B makes thread cols contiguous) ----
    float gamma = *gptr;
    const float* x2s = reinterpret_cast<const float*>(smem + SO_X2);
    const float* y2s = reinterpret_cast<const float*>(smem + SO_Y2);
    int grp = lane >> 2;
    int q = lane & 3;

    #pragma unroll
    for (int mt = 0; mt < 4; mt++) {
        int r0 = wm * 64 + mt * 16 + grp;
        float x2a = x2s[r0];
        float x2b = x2s[r0 + 8];
        #pragma unroll
        for (int p = 0; p < 2; p++) {
            int gcol = wn * 32 + p * 16 + q * 4;
            float y0 = y2s[gcol], y1 = y2s[gcol + 1];
            float y2v = y2s[gcol + 2], y3 = y2s[gcol + 3];
            const float* cA = acc[mt][2 * p];       // cols {0,1}
            const float* cB = acc[mt][2 * p + 1];   // cols {2,3}
            float4 o0, o1;
            o0.x = __expf(-gamma * fmaxf(x2a + y0  - 2.0f * cA[0], 0.0f));
            o0.y = __expf(-gamma * fmaxf(x2a + y1  - 2.0f * cA[1], 0.0f));
            o0.z = __expf(-gamma * fmaxf(x2a + y2v - 2.0f * cB[0], 0.0f));
            o0.w = __expf(-gamma * fmaxf(x2a + y3  - 2.0f * cB[1], 0.0f));
            o1.x = __expf(-gamma * fmaxf(x2b + y0  - 2.0f * cA[2], 0.0f));
            o1.y = __expf(-gamma * fmaxf(x2b + y1  - 2.0f * cA[3], 0.0f));
            o1.z = __expf(-gamma * fmaxf(x2b + y2v - 2.0f * cB[2], 0.0f));
            o1.w = __expf(-gamma * fmaxf(x2b + y3  - 2.0f * cB[3], 0.0f));
            *reinterpret_cast<float4*>(out + (size_t)(m0 + r0) * NC + n0 + gcol) = o0;
            *reinterpret_cast<float4*>(out + (size_t)(m0 + r0 + 8) * NC + n0 + gcol) = o1;
        }
    }
}

// ---------------------------------------------------------------------------
extern "C" void kernel_launch(void* const* d_in, const int* in_sizes, int n_in,
                              void* d_out, int out_size) {
    const float* x = (const float*)d_in[0];
    const float* y = (const float*)d_in[1];
    const float* g = (const float*)d_in[2];
    float* out = (float*)d_out;

    cudaFuncSetAttribute(rbf_gemm_kernel,
                         cudaFuncAttributeMaxDynamicSharedMemorySize, SMEM_TOTAL);

    prep_kernel<<<(NB + NC) / 8, 256>>>(x, y);

    dim3 grid(NC / TN, NB / TM);
    rbf_gemm_kernel<<<grid, 256, SMEM_TOTAL>>>(out, g);
}